// round 16
// baseline (speedup 1.0000x reference)
#include <cuda_runtime.h>
#include <cuda_bf16.h>
#include <math.h>

#define BB 4
#define CC 64
#define NN 64
#define NCANON 2050
#define NCTA   1025   // 2 matrices per CTA

typedef unsigned long long ull;

// ---------------------------------------------------------------------------
// Device scratch
// ---------------------------------------------------------------------------
__device__ float2 g_G[BB * NN * 3 * CC * CC];   // 25.2 MB: G[b][v][kh][i][j]
__device__ float  g_part[BB * NN * NN];         // weighted per-frequency logdets
__device__ int    g_cnt[BB];                    // completion counters (self-resetting)

// ---------------------------------------------------------------------------
// f32x2 packed helpers
// ---------------------------------------------------------------------------
__device__ __forceinline__ ull pk2(float lo, float hi) {
    ull r; asm("mov.b64 %0, {%1,%2};" : "=l"(r) : "f"(lo), "f"(hi)); return r;
}
__device__ __forceinline__ void upk2(ull v, float &lo, float &hi) {
    asm("mov.b64 {%0,%1}, %2;" : "=f"(lo), "=f"(hi) : "l"(v));
}
__device__ __forceinline__ ull fma2(ull a, ull b, ull c) {
    ull r; asm("fma.rn.f32x2 %0, %1, %2, %3;" : "=l"(r) : "l"(a), "l"(b), "l"(c));
    return r;
}
__device__ __forceinline__ ull sel4(ull a0, ull a1, ull a2, ull a3, int s) {
    ull x01 = (s & 1) ? a1 : a0;
    ull x23 = (s & 1) ? a3 : a2;
    return (s & 2) ? x23 : x01;
}
__device__ __forceinline__ void canon_map(int c, int &u, int &v, float &wt) {
    if (c < 1984)      { u = 1 + (c >> 6); v = c & 63; wt = 2.0f; }
    else if (c < 2017) { u = 0;  v = c - 1984; wt = (v == 0 || v == 32) ? 1.0f : 2.0f; }
    else               { u = 32; v = c - 2017; wt = (v == 0 || v == 32) ? 1.0f : 2.0f; }
}

// ---------------------------------------------------------------------------
// Kernel 1: G build
// ---------------------------------------------------------------------------
__global__ __launch_bounds__(256) void gbuild_kernel(const float* __restrict__ K) {
    int v = blockIdx.x & 63;
    int b = blockIdx.x >> 6;
    float th = -6.283185307179586f * (float)v / 64.0f;
    float s1, c1;
    sincosf(th, &s1, &c1);
    float c2 = c1 * c1 - s1 * s1;
    float s2 = 2.0f * s1 * c1;
    long long base = ((long long)(b * 64 + v)) * 3 * 4096;
    for (int e = threadIdx.x; e < 4096; e += 256) {
        int i = e >> 6, j = e & 63;
        const float* kp = K + ((size_t)(b * 64 + i) * 64 + j) * 9;
        float k[9];
#pragma unroll
        for (int t = 0; t < 9; t++) k[t] = kp[t];
        if (i == j) k[4] += 1.0f;
#pragma unroll
        for (int kh = 0; kh < 3; kh++) {
            float re = k[3 * kh] + k[3 * kh + 1] * c1 + k[3 * kh + 2] * c2;
            float im = k[3 * kh + 1] * s1 + k[3 * kh + 2] * s2;
            g_G[base + kh * 4096 + e] = make_float2(re, im);
        }
    }
}

// ---------------------------------------------------------------------------
// Kernel 2: circular conv (unchanged — known good)
// ---------------------------------------------------------------------------
__global__ __launch_bounds__(256) void conv_kernel(const float* __restrict__ x,
                                                   const float* __restrict__ K,
                                                   const float* __restrict__ bias,
                                                   float* __restrict__ out) {
    __shared__ float sIn[66 * 68];
    __shared__ float sTap[9];
    int co = blockIdx.x;
    int b  = blockIdx.y;
    int tid = threadIdx.x;
    int ty = tid >> 4, tx = tid & 15;
    int py = ty * 4, px = tx * 4;

    float acc[4][4];
#pragma unroll
    for (int r = 0; r < 4; r++)
#pragma unroll
        for (int c = 0; c < 4; c++) acc[r][c] = 0.0f;

    for (int ci = 0; ci < 64; ci++) {
        __syncthreads();
        const float* xp = x + (size_t)(b * 64 + ci) * 4096;
        for (int e = tid; e < 66 * 66; e += 256) {
            int rr = e / 66;
            int cc2 = e - rr * 66;
            int gy = (rr + 63) & 63;
            int gx = (cc2 + 63) & 63;
            sIn[rr * 68 + cc2] = xp[gy * 64 + gx];
        }
        if (tid < 9) {
            float t = K[((size_t)(b * 64 + co) * 64 + ci) * 9 + tid];
            if (ci == co && tid == 4) t += 1.0f;
            sTap[tid] = t;
        }
        __syncthreads();
        float tp[9];
#pragma unroll
        for (int t = 0; t < 9; t++) tp[t] = sTap[t];
        float patch[6][6];
#pragma unroll
        for (int dr = 0; dr < 6; dr++)
#pragma unroll
            for (int dc = 0; dc < 6; dc++)
                patch[dr][dc] = sIn[(py + dr) * 68 + px + dc];
#pragma unroll
        for (int r = 0; r < 4; r++)
#pragma unroll
            for (int c = 0; c < 4; c++) {
                float a = acc[r][c];
#pragma unroll
                for (int kh = 0; kh < 3; kh++)
#pragma unroll
                    for (int kw = 0; kw < 3; kw++)
                        a = fmaf(tp[kh * 3 + kw], patch[r + kh][c + kw], a);
                acc[r][c] = a;
            }
    }
    float bv = bias[b * 64 + co];
    float* op = out + (size_t)(b * 64 + co) * 4096;
#pragma unroll
    for (int r = 0; r < 4; r++)
#pragma unroll
        for (int c = 0; c < 4; c++)
            op[(py + r) * 64 + px + c] = acc[r][c] + bv;
}

// ---------------------------------------------------------------------------
// Kernel 3: DUAL complex 64x64 LU per CTA. 256 threads.
// Matrix 0: thread column group tx = tid>>4 (cols 4tx..4tx+3)
// Matrix 1: column group ctx = (tx+8)&15  -> owner warps staggered by 4
// Row group ty = tid&15 (rows 4ty..4ty+3) for both.
// 2 barriers/step shared by both matrices. Fused final reduction.
// ---------------------------------------------------------------------------
struct LuS {
    ull    rowV [2][2][64];   // [m][pb][j]
    ull    rowVs[2][2][64];
    ull    rowK [2][2][64];
    ull    colM [2][2][64];
    ull    candKey[2][2];     // [m][pb]
    float  pivN2[2][64];
    float  red[2][64];
    double dred[256];
};

__global__ __launch_bounds__(256, 2) void lu_kernel(float* __restrict__ out) {
    int b = blockIdx.y;
    int u0, v0, u1, v1;
    float wt0, wt1;
    canon_map(2 * blockIdx.x,     u0, v0, wt0);
    canon_map(2 * blockIdx.x + 1, u1, v1, wt1);

    int tid = threadIdx.x;
    int tx  = tid >> 4;            // m0 column group
    int ctx = (tx + 8) & 15;       // m1 column group
    int ty  = tid & 15;            // row group (both)
    int w   = tid >> 5;
    int lane = tid & 31;

    __shared__ union {
        float2 A[4096];
        LuS bf;
    } sm;

    // ---- build both matrices (staged via smem, coalesced G reads) ----
    ull acc0[4][4], acc1[4][4];
#pragma unroll
    for (int m = 0; m < 2; m++) {
        int u = m ? u1 : u0, v = m ? v1 : v0;
        const float2* __restrict__ Gb = g_G + (long long)((b * 64 + v) * 3) * 4096;
        float su, cu;
        sincosf(-6.283185307179586f * (float)u / 64.0f, &su, &cu);
        float cu2 = cu * cu - su * su;
        float su2 = 2.0f * su * cu;
#pragma unroll 4
        for (int e = tid; e < 4096; e += 256) {
            float2 g0 = Gb[e];
            float2 g1 = Gb[4096 + e];
            float2 g2 = Gb[8192 + e];
            float re = g0.x + cu * g1.x - su * g1.y + cu2 * g2.x - su2 * g2.y;
            float im = g0.y + cu * g1.y + su * g1.x + cu2 * g2.y + su2 * g2.x;
            sm.A[e] = make_float2(re, im);
        }
        __syncthreads();
        int cg = m ? ctx : tx;
#pragma unroll
        for (int r = 0; r < 4; r++)
#pragma unroll
            for (int c2 = 0; c2 < 4; c2++) {
                float2 t = sm.A[(4 * ty + r) * 64 + 4 * cg + c2];
                if (m) acc1[r][c2] = pk2(t.x, t.y);
                else   acc0[r][c2] = pk2(t.x, t.y);
            }
        __syncthreads();
    }

    for (int k = 0; k < 64; k++) {
        int pb  = k & 1;
        int c8  = k >> 2;        // owning column group index
        int kc  = k & 3;
        int kty = k >> 2;        // owning ty of row k
        int krl = k & 3;
        int ow0 = k >> 3;              // owner warp, matrix 0
        int ow1 = (ow0 + 4) & 7;       // owner warp, matrix 1 (staggered)
        bool act0 = (8 * w + 7 >= k);
        bool act1 = (8 * ((w + 4) & 7) + 7 >= k);
        int half = (c8 & 1) << 4;

        // ---- S1 matrix 0: owner warp pivot search + multipliers ----
        if (w == ow0) {
            ull vkr[4] = {0ull, 0ull, 0ull, 0ull};
            ull bestKey = 0ull;
            if (tx == c8) {
#pragma unroll
                for (int r = 0; r < 4; r++) {
                    vkr[r] = sel4(acc0[r][0], acc0[r][1], acc0[r][2], acc0[r][3], kc);
                    float re, im;
                    upk2(vkr[r], re, im);
                    float n2 = fmaf(re, re, im * im);
                    int i = 4 * ty + r;
                    ull key = ((ull)__float_as_uint(n2) << 32) | (ull)(64 - i);
                    if (i >= k && key > bestKey) bestKey = key;
                }
            }
#pragma unroll
            for (int off = 16; off >= 1; off >>= 1) {
                ull o = __shfl_xor_sync(0xffffffffu, bestKey, off);
                if (o > bestKey) bestKey = o;
            }
            int p = 64 - (int)(bestKey & 0xffffffffull);
            float bn = __uint_as_float((unsigned)(bestKey >> 32));
            if (lane == 0) {
                sm.bf.candKey[0][pb] = bestKey;
                sm.bf.pivN2[0][k] = bn;
            }
            ull cpk = sel4(vkr[0], vkr[1], vkr[2], vkr[3], p & 3);
            ull apk = __shfl_sync(0xffffffffu, cpk, half | (p >> 2));
            ull ckk = sel4(vkr[0], vkr[1], vkr[2], vkr[3], krl);
            ull akk = __shfl_sync(0xffffffffu, ckk, half | kty);
            if (tx == c8) {
                float pre, pim;
                upk2(apk, pre, pim);
                float inv = __fdividef(1.0f, bn);
                float ipre = pre * inv, ipim = -pim * inv;
#pragma unroll
                for (int r = 0; r < 4; r++) {
                    int i = 4 * ty + r;
                    ull a = (i == p) ? akk : vkr[r];
                    float are, aim;
                    upk2(a, are, aim);
                    float mr = are * ipre - aim * ipim;
                    float mi = are * ipim + aim * ipre;
                    if (i <= k) { mr = 0.0f; mi = 0.0f; }
                    sm.bf.colM[0][pb][i] = pk2(mr, mi);
                }
            }
        }
        // ---- S1 matrix 1 (different warp -> parallel with m0's S1) ----
        if (w == ow1) {
            ull vkr[4] = {0ull, 0ull, 0ull, 0ull};
            ull bestKey = 0ull;
            if (ctx == c8) {
#pragma unroll
                for (int r = 0; r < 4; r++) {
                    vkr[r] = sel4(acc1[r][0], acc1[r][1], acc1[r][2], acc1[r][3], kc);
                    float re, im;
                    upk2(vkr[r], re, im);
                    float n2 = fmaf(re, re, im * im);
                    int i = 4 * ty + r;
                    ull key = ((ull)__float_as_uint(n2) << 32) | (ull)(64 - i);
                    if (i >= k && key > bestKey) bestKey = key;
                }
            }
#pragma unroll
            for (int off = 16; off >= 1; off >>= 1) {
                ull o = __shfl_xor_sync(0xffffffffu, bestKey, off);
                if (o > bestKey) bestKey = o;
            }
            int p = 64 - (int)(bestKey & 0xffffffffull);
            float bn = __uint_as_float((unsigned)(bestKey >> 32));
            if (lane == 0) {
                sm.bf.candKey[1][pb] = bestKey;
                sm.bf.pivN2[1][k] = bn;
            }
            ull cpk = sel4(vkr[0], vkr[1], vkr[2], vkr[3], p & 3);
            ull apk = __shfl_sync(0xffffffffu, cpk, half | (p >> 2));
            ull ckk = sel4(vkr[0], vkr[1], vkr[2], vkr[3], krl);
            ull akk = __shfl_sync(0xffffffffu, ckk, half | kty);
            if (ctx == c8) {
                float pre, pim;
                upk2(apk, pre, pim);
                float inv = __fdividef(1.0f, bn);
                float ipre = pre * inv, ipim = -pim * inv;
#pragma unroll
                for (int r = 0; r < 4; r++) {
                    int i = 4 * ty + r;
                    ull a = (i == p) ? akk : vkr[r];
                    float are, aim;
                    upk2(a, are, aim);
                    float mr = are * ipre - aim * ipim;
                    float mi = are * ipim + aim * ipre;
                    if (i <= k) { mr = 0.0f; mi = 0.0f; }
                    sm.bf.colM[1][pb][i] = pk2(mr, mi);
                }
            }
        }
        // row-k staging
        if (ty == kty) {
            if (act0) {
#pragma unroll
                for (int r = 0; r < 4; r++)
                    if (r == krl)
#pragma unroll
                        for (int c2 = 0; c2 < 4; c2++)
                            sm.bf.rowK[0][pb][4 * tx + c2] = acc0[r][c2];
            }
            if (act1) {
#pragma unroll
                for (int r = 0; r < 4; r++)
                    if (r == krl)
#pragma unroll
                        for (int c2 = 0; c2 < 4; c2++)
                            sm.bf.rowK[1][pb][4 * ctx + c2] = acc1[r][c2];
            }
        }
        __syncthreads();   // B1

        // ---- S2: pivot rows publish ----
        int p0 = 64 - (int)(sm.bf.candKey[0][pb] & 0xffffffffull);
        int p1 = 64 - (int)(sm.bf.candKey[1][pb] & 0xffffffffull);
        if (act0 && ty == (p0 >> 2)) {
            int pl = p0 & 3;
#pragma unroll
            for (int r = 0; r < 4; r++)
                if (r == pl)
#pragma unroll
                    for (int c2 = 0; c2 < 4; c2++) {
                        ull vv = acc0[r][c2];
                        sm.bf.rowV[0][pb][4 * tx + c2] = vv;
                        float vr_, vi_;
                        upk2(vv, vr_, vi_);
                        sm.bf.rowVs[0][pb][4 * tx + c2] = pk2(vi_, -vr_);
                    }
        }
        if (act1 && ty == (p1 >> 2)) {
            int pl = p1 & 3;
#pragma unroll
            for (int r = 0; r < 4; r++)
                if (r == pl)
#pragma unroll
                    for (int c2 = 0; c2 < 4; c2++) {
                        ull vv = acc1[r][c2];
                        sm.bf.rowV[1][pb][4 * ctx + c2] = vv;
                        float vr_, vi_;
                        upk2(vv, vr_, vi_);
                        sm.bf.rowVs[1][pb][4 * ctx + c2] = pk2(vi_, -vr_);
                    }
        }
        __syncthreads();   // B2

        // ---- S3 matrix 0: swap + rank-1 update ----
        if (act0) {
            if (ty == kty) {
#pragma unroll
                for (int r = 0; r < 4; r++)
                    if (r == krl)
#pragma unroll
                        for (int c2 = 0; c2 < 4; c2++)
                            acc0[r][c2] = sm.bf.rowV[0][pb][4 * tx + c2];
            }
            if (p0 != k && ty == (p0 >> 2)) {
                int pl = p0 & 3;
#pragma unroll
                for (int r = 0; r < 4; r++)
                    if (r == pl)
#pragma unroll
                        for (int c2 = 0; c2 < 4; c2++)
                            acc0[r][c2] = sm.bf.rowK[0][pb][4 * tx + c2];
            }
            ull rv[4], rs[4];
#pragma unroll
            for (int c2 = 0; c2 < 4; c2++) {
                rv[c2] = sm.bf.rowV[0][pb][4 * tx + c2];
                rs[c2] = sm.bf.rowVs[0][pb][4 * tx + c2];
            }
#pragma unroll
            for (int r = 0; r < 4; r++) {
                ull m = sm.bf.colM[0][pb][4 * ty + r];
                float mr, mi;
                upk2(m, mr, mi);
                ull mrd = pk2(-mr, -mr);
                ull mid = pk2(mi, mi);
#pragma unroll
                for (int c2 = 0; c2 < 4; c2++) {
                    acc0[r][c2] = fma2(mrd, rv[c2], acc0[r][c2]);
                    acc0[r][c2] = fma2(mid, rs[c2], acc0[r][c2]);
                }
            }
        }
        // ---- S3 matrix 1 ----
        if (act1) {
            if (ty == kty) {
#pragma unroll
                for (int r = 0; r < 4; r++)
                    if (r == krl)
#pragma unroll
                        for (int c2 = 0; c2 < 4; c2++)
                            acc1[r][c2] = sm.bf.rowV[1][pb][4 * ctx + c2];
            }
            if (p1 != k && ty == (p1 >> 2)) {
                int pl = p1 & 3;
#pragma unroll
                for (int r = 0; r < 4; r++)
                    if (r == pl)
#pragma unroll
                        for (int c2 = 0; c2 < 4; c2++)
                            acc1[r][c2] = sm.bf.rowK[1][pb][4 * ctx + c2];
            }
            ull rv[4], rs[4];
#pragma unroll
            for (int c2 = 0; c2 < 4; c2++) {
                rv[c2] = sm.bf.rowV[1][pb][4 * ctx + c2];
                rs[c2] = sm.bf.rowVs[1][pb][4 * ctx + c2];
            }
#pragma unroll
            for (int r = 0; r < 4; r++) {
                ull m = sm.bf.colM[1][pb][4 * ty + r];
                float mr, mi;
                upk2(m, mr, mi);
                ull mrd = pk2(-mr, -mr);
                ull mid = pk2(mi, mi);
#pragma unroll
                for (int c2 = 0; c2 < 4; c2++) {
                    acc1[r][c2] = fma2(mrd, rv[c2], acc1[r][c2]);
                    acc1[r][c2] = fma2(mid, rs[c2], acc1[r][c2]);
                }
            }
        }
    }

    // ---- logs + per-frequency partials ----
    __syncthreads();
    if (tid < 64) {
        sm.bf.red[0][tid] = logf(sm.bf.pivN2[0][tid]);
        sm.bf.red[1][tid] = logf(sm.bf.pivN2[1][tid]);
    }
    __syncthreads();
    __shared__ int s_last;
    if (tid == 0) {
        float s0 = 0.0f, s1 = 0.0f;
#pragma unroll
        for (int t = 0; t < 64; t++) { s0 += sm.bf.red[0][t]; s1 += sm.bf.red[1][t]; }
        g_part[b * 4096 + u0 * 64 + v0] = wt0 * 0.5f * s0;
        g_part[b * 4096 + u1 * 64 + v1] = wt1 * 0.5f * s1;
        __threadfence();
        int old = atomicAdd(&g_cnt[b], 1);
        s_last = (old == NCTA - 1) ? 1 : 0;
    }
    __syncthreads();

    // ---- last CTA per sample: deterministic fixed-order reduction ----
    if (s_last) {
        __threadfence();
        double s = 0.0;
        for (int e = tid; e < 4096; e += 256)
            s += (double)__ldcg(&g_part[b * 4096 + e]);
        sm.bf.dred[tid] = s;
        __syncthreads();
        for (int st = 128; st > 0; st >>= 1) {
            if (tid < st) sm.bf.dred[tid] += sm.bf.dred[tid + st];
            __syncthreads();
        }
        if (tid == 0) {
            out[1048576 + b] = (float)sm.bf.dred[0];
            g_cnt[b] = 0;   // reset for next graph replay
        }
    }
}

// ---------------------------------------------------------------------------
extern "C" void kernel_launch(void* const* d_in, const int* in_sizes, int n_in,
                              void* d_out, int out_size) {
    const float* x = nullptr;
    const float* K = nullptr;
    const float* bias = nullptr;
    for (int i = 0; i < n_in; i++) {
        if (in_sizes[i] == 1048576)      x    = (const float*)d_in[i];
        else if (in_sizes[i] == 147456)  K    = (const float*)d_in[i];
        else if (in_sizes[i] == 256)     bias = (const float*)d_in[i];
    }
    float* out = (float*)d_out;

    gbuild_kernel<<<256, 256>>>(K);
    conv_kernel<<<dim3(64, 4), 256>>>(x, K, bias, out);
    lu_kernel<<<dim3(NCTA, 4), 256>>>(out);
}

// round 17
// speedup vs baseline: 1.6156x; 1.6156x over previous
#include <cuda_runtime.h>
#include <cuda_bf16.h>
#include <math.h>

#define BB 4
#define CC 64
#define NN 64
#define NCANON 2050

typedef unsigned long long ull;

// ---------------------------------------------------------------------------
// Device scratch
// ---------------------------------------------------------------------------
__device__ float2 g_G[BB * NN * 3 * CC * CC];   // 25.2 MB: G[b][v][kh][i][j]
__device__ float  g_part[BB * NN * NN];         // weighted per-frequency logdets (zero-init)
__device__ int    g_cnt[BB];                    // completion counters (self-resetting)

// ---------------------------------------------------------------------------
// f32x2 packed helpers
// ---------------------------------------------------------------------------
__device__ __forceinline__ ull pk2(float lo, float hi) {
    ull r; asm("mov.b64 %0, {%1,%2};" : "=l"(r) : "f"(lo), "f"(hi)); return r;
}
__device__ __forceinline__ ull fma2(ull a, ull b, ull c) {
    ull r; asm("fma.rn.f32x2 %0, %1, %2, %3;" : "=l"(r) : "l"(a), "l"(b), "l"(c));
    return r;
}
__device__ __forceinline__ void upk2(ull v, float &lo, float &hi) {
    asm("mov.b64 {%0,%1}, %2;" : "=f"(lo), "=f"(hi) : "l"(v));
}
__device__ __forceinline__ void canon_map(int c, int &u, int &v, float &wt) {
    if (c < 1984)      { u = 1 + (c >> 6); v = c & 63; wt = 2.0f; }
    else if (c < 2017) { u = 0;  v = c - 1984; wt = (v == 0 || v == 32) ? 1.0f : 2.0f; }
    else               { u = 32; v = c - 2017; wt = (v == 0 || v == 32) ? 1.0f : 2.0f; }
}

// ---------------------------------------------------------------------------
// Kernel 1: G build
// ---------------------------------------------------------------------------
__global__ __launch_bounds__(256) void gbuild_kernel(const float* __restrict__ K) {
    int v = blockIdx.x & 63;
    int b = blockIdx.x >> 6;
    float th = -6.283185307179586f * (float)v / 64.0f;
    float s1, c1;
    sincosf(th, &s1, &c1);
    float c2 = c1 * c1 - s1 * s1;
    float s2 = 2.0f * s1 * c1;
    long long base = ((long long)(b * 64 + v)) * 3 * 4096;
    for (int e = threadIdx.x; e < 4096; e += 256) {
        int i = e >> 6, j = e & 63;
        const float* kp = K + ((size_t)(b * 64 + i) * 64 + j) * 9;
        float k[9];
#pragma unroll
        for (int t = 0; t < 9; t++) k[t] = kp[t];
        if (i == j) k[4] += 1.0f;
#pragma unroll
        for (int kh = 0; kh < 3; kh++) {
            float re = k[3 * kh] + k[3 * kh + 1] * c1 + k[3 * kh + 2] * c2;
            float im = k[3 * kh + 1] * s1 + k[3 * kh + 2] * s2;
            g_G[base + kh * 4096 + e] = make_float2(re, im);
        }
    }
}

// ---------------------------------------------------------------------------
// Kernel 2: circular conv (unchanged — known good)
// ---------------------------------------------------------------------------
__global__ __launch_bounds__(256) void conv_kernel(const float* __restrict__ x,
                                                   const float* __restrict__ K,
                                                   const float* __restrict__ bias,
                                                   float* __restrict__ out) {
    __shared__ float sIn[66 * 68];
    __shared__ float sTap[9];
    int co = blockIdx.x;
    int b  = blockIdx.y;
    int tid = threadIdx.x;
    int ty = tid >> 4, tx = tid & 15;
    int py = ty * 4, px = tx * 4;

    float acc[4][4];
#pragma unroll
    for (int r = 0; r < 4; r++)
#pragma unroll
        for (int c = 0; c < 4; c++) acc[r][c] = 0.0f;

    for (int ci = 0; ci < 64; ci++) {
        __syncthreads();
        const float* xp = x + (size_t)(b * 64 + ci) * 4096;
        for (int e = tid; e < 66 * 66; e += 256) {
            int rr = e / 66;
            int cc2 = e - rr * 66;
            int gy = (rr + 63) & 63;
            int gx = (cc2 + 63) & 63;
            sIn[rr * 68 + cc2] = xp[gy * 64 + gx];
        }
        if (tid < 9) {
            float t = K[((size_t)(b * 64 + co) * 64 + ci) * 9 + tid];
            if (ci == co && tid == 4) t += 1.0f;
            sTap[tid] = t;
        }
        __syncthreads();
        float tp[9];
#pragma unroll
        for (int t = 0; t < 9; t++) tp[t] = sTap[t];
        float patch[6][6];
#pragma unroll
        for (int dr = 0; dr < 6; dr++)
#pragma unroll
            for (int dc = 0; dc < 6; dc++)
                patch[dr][dc] = sIn[(py + dr) * 68 + px + dc];
#pragma unroll
        for (int r = 0; r < 4; r++)
#pragma unroll
            for (int c = 0; c < 4; c++) {
                float a = acc[r][c];
#pragma unroll
                for (int kh = 0; kh < 3; kh++)
#pragma unroll
                    for (int kw = 0; kw < 3; kw++)
                        a = fmaf(tp[kh * 3 + kw], patch[r + kh][c + kw], a);
                acc[r][c] = a;
            }
    }
    float bv = bias[b * 64 + co];
    float* op = out + (size_t)(b * 64 + co) * 4096;
#pragma unroll
    for (int r = 0; r < 4; r++)
#pragma unroll
        for (int c = 0; c < 4; c++)
            op[(py + r) * 64 + px + c] = acc[r][c] + bv;
}

// ---------------------------------------------------------------------------
// Kernel 3: blocked complex 64x64 LU (NB=8) with partial pivoting, in smem.
// Panel: warp 0 alone (redux pivot search, no CTA barrier per micro-step).
// Tri-solve: threads < trailing cols. GEMM: warps s+1..7, 4x4 register tiles.
// 3 barriers per block step (24 total). Fused per-sample reduction.
// ---------------------------------------------------------------------------
__global__ __launch_bounds__(256) void lu_kernel(float* __restrict__ out, int b) {
    __shared__ __align__(16) float2 As[64 * 66];   // stride 66 -> 16B-aligned rows
    __shared__ __align__(16) float2 Ls[8 * 64];    // L block, col-major compact
    __shared__ __align__(16) float2 Us[8 * 66];    // U block, row-major compact
    __shared__ float pivN2[64];
    __shared__ float red[64];
    __shared__ double dred[256];
    __shared__ int s_last;

    int cidx = blockIdx.x;
    int u, v;
    float wt;
    canon_map(cidx, u, v, wt);

    int tid  = threadIdx.x;
    int w    = tid >> 5;
    int lane = tid & 31;

    // ---- build A = sum_kh G[b,v,kh] * wu^kh into smem (coalesced reads) ----
    {
        const float2* __restrict__ Gb = g_G + (long long)((b * 64 + v) * 3) * 4096;
        float su, cu;
        sincosf(-6.283185307179586f * (float)u / 64.0f, &su, &cu);
        float cu2 = cu * cu - su * su;
        float su2 = 2.0f * su * cu;
#pragma unroll 4
        for (int e = tid; e < 4096; e += 256) {
            float2 g0 = Gb[e];
            float2 g1 = Gb[4096 + e];
            float2 g2 = Gb[8192 + e];
            float re = g0.x + cu * g1.x - su * g1.y + cu2 * g2.x - su2 * g2.y;
            float im = g0.y + cu * g1.y + su * g1.x + cu2 * g2.y + su2 * g2.x;
            As[(e >> 6) * 66 + (e & 63)] = make_float2(re, im);
        }
    }
    __syncthreads();

    for (int s = 0; s < 8; s++) {
        // ================= panel factorization: warp 0 only =================
        if (w == 0) {
#pragma unroll
            for (int t = 0; t < 8; t++) {
                int k = 8 * s + t;
                // pivot search over rows k..63 of column k
                int rowA = k + lane;
                int rowB = k + 32 + lane;
                float nA = -1.0f, nB = -1.0f;
                if (rowA < 64) {
                    float2 a = As[rowA * 66 + k];
                    nA = fmaf(a.x, a.x, a.y * a.y);
                }
                if (rowB < 64) {
                    float2 a = As[rowB * 66 + k];
                    nB = fmaf(a.x, a.x, a.y * a.y);
                }
                float nb; int rb;
                if (nB > nA) { nb = nB; rb = rowB; } else { nb = nA; rb = rowA; }
                unsigned key = (nb >= 0.0f) ? __float_as_uint(nb) : 0u;
                unsigned m = __reduce_max_sync(0xffffffffu, key);
                unsigned ball = __ballot_sync(0xffffffffu, key == m);
                int src = __ffs(ball) - 1;
                int p = __shfl_sync(0xffffffffu, rb, src);
                float bn = __uint_as_float(m);
                if (lane == 0) pivN2[k] = bn;

                // swap rows k <-> p over cols [8s, 64)
                if (p != k) {
                    for (int c = 8 * s + lane; c < 64; c += 32) {
                        float2 va = As[k * 66 + c];
                        float2 vb = As[p * 66 + c];
                        As[k * 66 + c] = vb;
                        As[p * 66 + c] = va;
                    }
                    __syncwarp();
                }

                // reciprocal pivot (all lanes, from swapped A[k][k])
                float2 pv = As[k * 66 + k];   // broadcast
                float inv = __fdividef(1.0f, bn);
                float ipre = pv.x * inv, ipim = -pv.y * inv;

                // preload row-k entries for remaining panel cols (broadcast)
                float2 uc[8];
#pragma unroll
                for (int c = t + 1; c < 8; c++) uc[c] = As[k * 66 + 8 * s + c];

                // scale column + rank-1 update of remaining panel cols
#pragma unroll
                for (int rr = 0; rr < 2; rr++) {
                    int i = k + 1 + lane + 32 * rr;
                    if (i < 64) {
                        float2 a = As[i * 66 + k];
                        float mr = a.x * ipre - a.y * ipim;
                        float mi = a.x * ipim + a.y * ipre;
                        As[i * 66 + k] = make_float2(mr, mi);
#pragma unroll
                        for (int c = t + 1; c < 8; c++) {
                            float2 x = As[i * 66 + 8 * s + c];
                            x.x -= mr * uc[c].x - mi * uc[c].y;
                            x.y -= mr * uc[c].y + mi * uc[c].x;
                            As[i * 66 + 8 * s + c] = x;
                        }
                    }
                }
                __syncwarp();
            }
        }
        __syncthreads();

        if (s == 7) break;
        int trail = 8 * (s + 1);
        int ncols = 64 - trail;

        // ======= stage L block (col-major compact) + triangular solve U =======
        for (int e = tid; e < 512; e += 256) {
            int c = e >> 6, i = e & 63;
            Ls[c * 64 + i] = As[i * 66 + 8 * s + c];
        }
        if (tid < ncols) {
            int j = trail + tid;
            float2 uu[8];
#pragma unroll
            for (int t = 0; t < 8; t++) {
                float2 val = As[(8 * s + t) * 66 + j];
#pragma unroll
                for (int m2 = 0; m2 < t; m2++) {
                    float2 lm = As[(8 * s + t) * 66 + 8 * s + m2];  // broadcast
                    val.x -= lm.x * uu[m2].x - lm.y * uu[m2].y;
                    val.y -= lm.x * uu[m2].y + lm.y * uu[m2].x;
                }
                uu[t] = val;
                Us[t * 66 + j] = val;
            }
        }
        __syncthreads();

        // ================= GEMM: A22 -= L21 * U12 (warps s+1..7) =============
        if (w > s) {
            int row0 = 8 * w + 4 * (lane >> 4);
            int c0 = trail + 4 * (lane & 15);
            if (c0 < 64) {
                ull acc[4][4];
#pragma unroll
                for (int r = 0; r < 4; r++) {
                    float4 p0 = *(const float4*)&As[(row0 + r) * 66 + c0];
                    float4 p1 = *(const float4*)&As[(row0 + r) * 66 + c0 + 2];
                    acc[r][0] = pk2(p0.x, p0.y); acc[r][1] = pk2(p0.z, p0.w);
                    acc[r][2] = pk2(p1.x, p1.y); acc[r][3] = pk2(p1.z, p1.w);
                }
#pragma unroll
                for (int k2 = 0; k2 < 8; k2++) {
                    float4 l0 = *(const float4*)&Ls[k2 * 64 + row0];
                    float4 l1 = *(const float4*)&Ls[k2 * 64 + row0 + 2];
                    float4 u0 = *(const float4*)&Us[k2 * 66 + c0];
                    float4 u1 = *(const float4*)&Us[k2 * 66 + c0 + 2];
                    float lr[4] = {l0.x, l0.z, l1.x, l1.z};
                    float li[4] = {l0.y, l0.w, l1.y, l1.w};
                    ull uv[4] = {pk2(u0.x, u0.y), pk2(u0.z, u0.w),
                                 pk2(u1.x, u1.y), pk2(u1.z, u1.w)};
                    ull us2[4] = {pk2(u0.y, -u0.x), pk2(u0.w, -u0.z),
                                  pk2(u1.y, -u1.x), pk2(u1.w, -u1.z)};
#pragma unroll
                    for (int r = 0; r < 4; r++) {
                        ull mrd = pk2(-lr[r], -lr[r]);
                        ull mid = pk2(li[r], li[r]);
#pragma unroll
                        for (int c = 0; c < 4; c++) {
                            acc[r][c] = fma2(mrd, uv[c], acc[r][c]);
                            acc[r][c] = fma2(mid, us2[c], acc[r][c]);
                        }
                    }
                }
#pragma unroll
                for (int r = 0; r < 4; r++) {
                    float x0, y0, x1, y1, x2, y2, x3, y3;
                    upk2(acc[r][0], x0, y0); upk2(acc[r][1], x1, y1);
                    upk2(acc[r][2], x2, y2); upk2(acc[r][3], x3, y3);
                    *(float4*)&As[(row0 + r) * 66 + c0]     = make_float4(x0, y0, x1, y1);
                    *(float4*)&As[(row0 + r) * 66 + c0 + 2] = make_float4(x2, y2, x3, y3);
                }
            }
        }
        __syncthreads();
    }

    // ---- logs + per-frequency partial ----
    __syncthreads();
    if (tid < 64) red[tid] = logf(pivN2[tid]);
    __syncthreads();
    if (tid == 0) {
        float s = 0.0f;
#pragma unroll
        for (int t = 0; t < 64; t++) s += red[t];
        g_part[b * 4096 + u * 64 + v] = wt * 0.5f * s;
        __threadfence();
        int old = atomicAdd(&g_cnt[b], 1);
        s_last = (old == NCANON - 1) ? 1 : 0;
    }
    __syncthreads();

    // ---- last CTA per sample: deterministic fixed-order reduction ----
    if (s_last) {
        __threadfence();
        double s = 0.0;
        for (int e = tid; e < 4096; e += 256)
            s += (double)__ldcg(&g_part[b * 4096 + e]);
        dred[tid] = s;
        __syncthreads();
        for (int st = 128; st > 0; st >>= 1) {
            if (tid < st) dred[tid] += dred[tid + st];
            __syncthreads();
        }
        if (tid == 0) {
            out[1048576 + b] = (float)dred[0];
            g_cnt[b] = 0;   // reset for next graph replay
        }
    }
}

// ---------------------------------------------------------------------------
extern "C" void kernel_launch(void* const* d_in, const int* in_sizes, int n_in,
                              void* d_out, int out_size) {
    const float* x = nullptr;
    const float* K = nullptr;
    const float* bias = nullptr;
    for (int i = 0; i < n_in; i++) {
        if (in_sizes[i] == 1048576)      x    = (const float*)d_in[i];
        else if (in_sizes[i] == 147456)  K    = (const float*)d_in[i];
        else if (in_sizes[i] == 256)     bias = (const float*)d_in[i];
    }
    float* out = (float*)d_out;

    gbuild_kernel<<<256, 256>>>(K);
    conv_kernel<<<dim3(64, 4), 256>>>(x, K, bias, out);
    // 4 separate lu launches (one per sample) — also aligns ncu's capture slot
    // (skip-5, capture-6th) onto a lu launch for real stall data next round.
    for (int b = 0; b < BB; b++)
        lu_kernel<<<NCANON, 256>>>(out, b);
}